// round 8
// baseline (speedup 1.0000x reference)
#include <cuda_runtime.h>
#include <math.h>

// Problem constants (fixed by reference setup_inputs)
#define NB 32
#define BV 516
#define NS 2048
#define NROWS (NB * BV)     // 16512 (b,v) rows
#define NCOLS (NB * NS)     // 65536 (b,s) columns
#define NVCHUNK 12
#define VCHUNK 43           // 12 * 43 = 516
#define NSHALF 2            // two 1024-column halves
#define TPB1 256
#define TPBC 128
#define NBLKC (NCOLS / TPBC) // 512 comb blocks
#define NEG_BIG (-1e30f)

// Scratch (no allocations allowed -> __device__ globals).
// 16B alignment is required for the float4/uchar4 vector accesses.
__device__ float  g_rowpart[NSHALF * NROWS];   // per-s-half row sums of exp
__device__ float  g_lse[NROWS];
__device__ float  g_delta[NB];
__device__ __align__(16) float  g_psum[NVCHUNK * NCOLS];  // per-chunk column sum of exp
__device__ __align__(16) float  g_cv1[NVCHUNK * NCOLS];   // chunk top-1 value per column
__device__ __align__(16) float  g_cv2[NVCHUNK * NCOLS];   // chunk top-2 value per column
__device__ __align__(16) unsigned char g_ci1[NVCHUNK * NCOLS]; // chunk-local idx of top-1
__device__ double g_part_nll[NBLKC];
__device__ double g_part_mask[NBLKC];
__device__ unsigned int g_arrive;               // zero-init; reset each run

// ---------------------------------------------------------------------------
// Kernel 1 (the only full read): block = (s-half of 1024 cols, v-chunk of 43
// rows, batch). Thread owns 4 contiguous s-columns (one LDG.128 per row).
// Column sums + per-column top-2 are THREAD-PRIVATE; row sums cost 5 SHFL
// per 128 elements (once per row per warp). All reductions fixed-order.
// ---------------------------------------------------------------------------
__global__ void __launch_bounds__(TPB1) k_main(const float* __restrict__ out) {
    const int sh_ = blockIdx.x;            // s half (0/1)
    const int c   = blockIdx.y;            // v chunk
    const int b   = blockIdx.z;
    const int t   = threadIdx.x;
    const int lane = t & 31, w = t >> 5;
    const int v0 = c * VCHUNK;
    const int s0 = sh_ * 1024 + t * 4;

    const float* p = out + ((size_t)b * BV + v0) * NS + s0;

    __shared__ float shrow[VCHUNK][8];     // per-warp row partials

    float cs0 = 0.f, cs1 = 0.f, cs2 = 0.f, cs3 = 0.f;
    float t1[4], t2[4];
    int   j1[4];
    #pragma unroll
    for (int j = 0; j < 4; j++) { t1[j] = NEG_BIG; t2[j] = NEG_BIG; j1[j] = 0; }

    float4 xa = __ldg(reinterpret_cast<const float4*>(p));

    #pragma unroll 1
    for (int r = 0; r < VCHUNK; r++) {
        const float4 xc = xa;
        if (r + 1 < VCHUNK) {
            p += NS;
            xa = __ldg(reinterpret_cast<const float4*>(p));
        }
        const float e0 = __expf(xc.x), e1 = __expf(xc.y);
        const float e2 = __expf(xc.z), e3 = __expf(xc.w);
        cs0 += e0; cs1 += e1; cs2 += e2; cs3 += e3;

        float rq = (e0 + e1) + (e2 + e3);
        rq += __shfl_down_sync(0xffffffffu, rq, 16);
        rq += __shfl_down_sync(0xffffffffu, rq, 8);
        rq += __shfl_down_sync(0xffffffffu, rq, 4);
        rq += __shfl_down_sync(0xffffffffu, rq, 2);
        rq += __shfl_down_sync(0xffffffffu, rq, 1);
        if (lane == 0) shrow[r][w] = rq;

        const float xv[4] = {xc.x, xc.y, xc.z, xc.w};
        #pragma unroll
        for (int j = 0; j < 4; j++) {
            if (xv[j] > t2[j]) {
                if (xv[j] > t1[j]) { t2[j] = t1[j]; t1[j] = xv[j]; j1[j] = r; }
                else               { t2[j] = xv[j]; }
            }
        }
    }
    __syncthreads();

    // fixed-order combine of 8 per-warp row partials (deterministic)
    if (t < VCHUNK) {
        float rs = 0.f;
        #pragma unroll
        for (int w8 = 0; w8 < 8; w8++) rs += shrow[t][w8];
        g_rowpart[sh_ * NROWS + b * BV + v0 + t] = rs;
    }

    // vectorized column outputs (16B-aligned: s0 is a multiple of 4)
    const int n = b * NS + s0;
    *reinterpret_cast<float4*>(g_psum + c * NCOLS + n) = make_float4(cs0, cs1, cs2, cs3);
    *reinterpret_cast<float4*>(g_cv1  + c * NCOLS + n) = make_float4(t1[0], t1[1], t1[2], t1[3]);
    *reinterpret_cast<float4*>(g_cv2  + c * NCOLS + n) = make_float4(t2[0], t2[1], t2[2], t2[3]);
    *reinterpret_cast<uchar4*>(g_ci1  + c * NCOLS + n) =
        make_uchar4((unsigned char)j1[0], (unsigned char)j1[1],
                    (unsigned char)j1[2], (unsigned char)j1[3]);
}

// ---------------------------------------------------------------------------
// Kernel 2 (tiny): rowsum = half0 + half1 (fixed order) -> lse = log,
// plus per-batch lse spread Delta_b.
// ---------------------------------------------------------------------------
__global__ void __launch_bounds__(512) k_lse(void) {
    const int b = blockIdx.x;
    const int t = threadIdx.x;
    float lmin = 1e30f, lmax = NEG_BIG;

    for (int v = t; v < BV; v += 512) {
        const float rs = g_rowpart[b * BV + v] + g_rowpart[NROWS + b * BV + v];
        const float l = __logf(rs);
        g_lse[b * BV + v] = l;
        lmin = fminf(lmin, l);
        lmax = fmaxf(lmax, l);
    }
    #pragma unroll
    for (int o = 16; o; o >>= 1) {
        lmin = fminf(lmin, __shfl_down_sync(0xffffffffu, lmin, o));
        lmax = fmaxf(lmax, __shfl_down_sync(0xffffffffu, lmax, o));
    }
    __shared__ float smin[16], smax[16];
    if ((t & 31) == 0) { smin[t >> 5] = lmin; smax[t >> 5] = lmax; }
    __syncthreads();
    if (t == 0) {
        float mn = smin[0], mx = smax[0];
        #pragma unroll
        for (int i = 1; i < 16; i++) { mn = fminf(mn, smin[i]); mx = fmaxf(mx, smax[i]); }
        g_delta[b] = mx - mn;
    }
}

// ---------------------------------------------------------------------------
// Kernel 3: per column -> nll from 12 chunk sums; argmax from chunk top-1s.
// Exact: winner must satisfy x >= m - Delta_b; if a chunk's 2nd value clears
// that bar, deterministically rescan just that chunk (43 strided loads).
// Then penalty mask, deterministic reduction, fused last-block finalize.
// ---------------------------------------------------------------------------
__global__ void __launch_bounds__(TPBC) k_comb(
    const float* __restrict__ out,
    const int*   __restrict__ target,
    const int*   __restrict__ ttype,
    const float* __restrict__ tvalue,
    const float* __restrict__ coeff,
    const float* __restrict__ harm,
    float*       __restrict__ res)
{
    const int n = blockIdx.x * TPBC + threadIdx.x;   // 0..65535
    const int b = n >> 11;
    const int s = n & (NS - 1);
    const float* lse = g_lse + b * BV;

    float sum = 0.f, m = NEG_BIG;
    float v1[NVCHUNK], v2[NVCHUNK];
    int   i1[NVCHUNK];
    #pragma unroll
    for (int c = 0; c < NVCHUNK; c++) {
        sum += g_psum[c * NCOLS + n];
        v1[c] = g_cv1[c * NCOLS + n];
        v2[c] = g_cv2[c * NCOLS + n];
        i1[c] = g_ci1[c * NCOLS + n];
        m = fmaxf(m, v1[c]);
    }
    const float thr = m - g_delta[b];

    float best = NEG_BIG;
    int   bi   = 0;
    #pragma unroll 1
    for (int c = 0; c < NVCHUNK; c++) {
        if (v2[c] >= thr) {
            // rare: chunk may hide candidates beyond top-1 -> exact rescan
            const float* colp = out + ((size_t)b * BV + c * VCHUNK) * NS + s;
            for (int r = 0; r < VCHUNK; r++) {
                const float sc_ = __ldg(colp + (size_t)r * NS) - __ldg(lse + c * VCHUNK + r);
                if (sc_ > best) { best = sc_; bi = c * VCHUNK + r; }
            }
        } else {
            const int v = c * VCHUNK + i1[c];
            const float sc_ = v1[c] - __ldg(lse + v);
            if (sc_ > best) { best = sc_; bi = v; }
        }
    }

    const int tgt = target[n];
    const float t_logit = __ldg(out + ((size_t)b * BV + tgt) * NS + s);
    const float nll = __logf(sum) - t_logit;

    // penalty mask
    const int   pt = __ldg(ttype  + bi), qt = __ldg(ttype  + tgt);
    const float pv = __ldg(tvalue + bi), qv = __ldg(tvalue + tgt);
    const float d  = fabsf(pv - qv);

    float pw = (d == 7.0f) ? __ldg(harm + 0)
             : (d == 5.0f) ? __ldg(harm + 1)
             : (d == 3.0f) ? __ldg(harm + 2)
             : (d == 4.0f) ? __ldg(harm + 3)
             : (d == 1.0f) ? __ldg(harm + 4)
             : (d == 2.0f) ? __ldg(harm + 5)
             :               __ldg(harm + 6);

    float w;
    if (pt != qt)       w = __ldg(coeff + 0);
    else if (pt == 0)   w = pw;
    else if (pt == 1)   w = __ldg(coeff + 1) * d * (1.0f / 160.0f);
    else if (pt == 2)   w = __ldg(coeff + 2) * d * (1.0f / 100.0f);
    else                w = __ldg(coeff + 3) * d * (1.0f / 128.0f);

    // block reduction (double), fixed order
    double dn = (double)nll, dm = (double)w;
    #pragma unroll
    for (int o = 16; o; o >>= 1) {
        dn += __shfl_down_sync(0xffffffffu, dn, o);
        dm += __shfl_down_sync(0xffffffffu, dm, o);
    }
    __shared__ double shn[TPBC / 32], shm[TPBC / 32];
    const int wid = threadIdx.x >> 5;
    if ((threadIdx.x & 31) == 0) { shn[wid] = dn; shm[wid] = dm; }
    __syncthreads();

    __shared__ bool s_last;
    if (threadIdx.x == 0) {
        double an = 0.0, am = 0.0;
        #pragma unroll
        for (int i = 0; i < TPBC / 32; i++) { an += shn[i]; am += shm[i]; }
        g_part_nll[blockIdx.x]  = an;
        g_part_mask[blockIdx.x] = am;
        __threadfence();
        unsigned int prev = atomicAdd(&g_arrive, 1u);
        s_last = (prev == NBLKC - 1);
    }
    __syncthreads();

    if (s_last) {
        const int t = threadIdx.x;
        double an = 0.0, am = 0.0;
        #pragma unroll
        for (int k = 0; k < NBLKC / TPBC; k++) {
            an += g_part_nll[t + k * TPBC];
            am += g_part_mask[t + k * TPBC];
        }
        #pragma unroll
        for (int o = 16; o; o >>= 1) {
            an += __shfl_down_sync(0xffffffffu, an, o);
            am += __shfl_down_sync(0xffffffffu, am, o);
        }
        if ((t & 31) == 0) { shn[t >> 5] = an; shm[t >> 5] = am; }
        __syncthreads();
        if (t == 0) {
            double fn = 0.0, fm = 0.0;
            #pragma unroll
            for (int i = 0; i < TPBC / 32; i++) { fn += shn[i]; fm += shm[i]; }
            const double inv = 1.0 / (double)NCOLS;
            const double loss = fn * inv;
            res[0] = (float)(loss * (1.0 + fm * inv));
            g_arrive = 0;   // reset for next graph replay
        }
    }
}

extern "C" void kernel_launch(void* const* d_in, const int* in_sizes, int n_in,
                              void* d_out, int out_size)
{
    const float* output  = (const float*)d_in[0];   // [32, 516, 2048] f32
    const int*   target  = (const int*)  d_in[1];   // [32, 2048] i32
    const int*   ttype   = (const int*)  d_in[2];   // [516] i32
    const float* tvalue  = (const float*)d_in[3];   // [516] f32
    const float* coeff   = (const float*)d_in[4];   // [4] f32
    const float* harm    = (const float*)d_in[5];   // [7] f32
    float* out = (float*)d_out;

    k_main<<<dim3(NSHALF, NVCHUNK, NB), TPB1>>>(output);
    k_lse<<<NB, 512>>>();
    k_comb<<<NBLKC, TPBC>>>(output, target, ttype, tvalue, coeff, harm, out);
}

// round 9
// speedup vs baseline: 2.0912x; 2.0912x over previous
#include <cuda_runtime.h>
#include <math.h>

// Problem constants (fixed by reference setup_inputs)
#define NB 32
#define BV 516
#define NS 2048
#define NROWS (NB * BV)     // 16512
#define NCOLS (NB * NS)     // 65536
#define TPB 256
#define PROWS 4
#define NPROD_PER_B (BV / PROWS)    // 129 producer blocks per batch
#define NPROD (NPROD_PER_B * NB)    // 4128
#define CV 172                       // consumer vocab-chunk (3 * 172 = 516)
#define NCH 3
#define SCW 256                      // columns per consumer block
#define NSC (NS / SCW)               // 8
#define NCONS_PER_B (NSC * NCH)      // 24
#define NCONS (NCONS_PER_B * NB)     // 768
#define NTICK (NPROD + NCONS)        // 4896
#define TPBC 128
#define NBLKC (NCOLS / TPBC)         // 512 comb blocks
#define NEG_BIG (-1e30f)

// Scratch (no allocations allowed -> __device__ globals)
__device__ float    g_lse[NROWS];
__device__ unsigned g_done[NB];      // producers finished per batch
__device__ unsigned g_ticket;
__device__ __align__(16) float g_psum [NCH * NCOLS];
__device__ __align__(16) float g_pbest[NCH * NCOLS];
__device__ int      g_pbi [NCH * NCOLS];
__device__ double   g_part_nll[NBLKC];
__device__ double   g_part_mask[NBLKC];
__device__ unsigned g_arrive;

// cum(b): tickets before segment b. Segment b = 129 producers of batch b,
// then (for b>=2) 24 consumers of batch b-2. Trailing 48 consumers (b=30,31).
__device__ __forceinline__ int cum_seg(int b) {
    return 129 * b + 24 * (b >= 2 ? b - 2 : 0);
}

// ---------------------------------------------------------------------------
// Reset counters each graph replay (runs before k_fused).
// ---------------------------------------------------------------------------
__global__ void k_reset() {
    if (threadIdx.x == 0) { g_ticket = 0u; g_arrive = 0u; }
    if (threadIdx.x < NB) g_done[threadIdx.x] = 0u;
}

// ---------------------------------------------------------------------------
// Fused pipelined kernel. Each block takes a ticket (start-order). Tickets
// interleave producers (row LSE, 4 rows/block) with consumers (column pass
// over a 172-row x 256-col tile) lagging 2 batches -> consumer reads hit L2.
// Deadlock-free: consumers wait only on strictly-smaller tickets; producers
// never wait (decoupled-lookback argument).
// ---------------------------------------------------------------------------
__global__ void __launch_bounds__(TPB) k_fused(const float* __restrict__ out) {
    __shared__ unsigned s_ticket;
    if (threadIdx.x == 0) s_ticket = atomicAdd(&g_ticket, 1u);
    __syncthreads();
    const int t   = (int)s_ticket;
    const int tid = threadIdx.x;

    // ---- decode ticket -> role ----
    int prod_b = -1, prod_p = 0;     // producer: batch, 4-row group
    int cons_b = -1, cons_c = 0, cons_sc = 0;
    if (t < cum_seg(32)) {                        // 4848
        int b = 0;
        while (b < 31 && t >= cum_seg(b + 1)) b++;
        const int loc = t - cum_seg(b);
        if (loc < 129) { prod_b = b; prod_p = loc; }
        else { cons_b = b - 2; const int ci = loc - 129; cons_c = ci >> 3; cons_sc = ci & 7; }
    } else {
        const int idx = t - cum_seg(32);
        cons_b = 30 + idx / 24;
        const int ci = idx % 24;
        cons_c = ci >> 3; cons_sc = ci & 7;
    }

    if (prod_b >= 0) {
        // ================= producer: LSE of 4 rows (proven R5 body) =======
        const int r0 = prod_b * BV + 4 * prod_p;           // global row base
        const float4* p = reinterpret_cast<const float4*>(out) + (size_t)r0 * (NS / 4);

        float4 x[8];
        #pragma unroll
        for (int k = 0; k < 4; k++) {
            x[2 * k]     = __ldg(p + k * 512 + tid);
            x[2 * k + 1] = __ldg(p + k * 512 + 256 + tid);
        }
        float s[4];
        #pragma unroll
        for (int k = 0; k < 4; k++) {
            float4 a = x[2 * k], bq = x[2 * k + 1];
            s[k] = __expf(a.x) + __expf(a.y) + __expf(a.z) + __expf(a.w)
                 + __expf(bq.x) + __expf(bq.y) + __expf(bq.z) + __expf(bq.w);
        }
        #pragma unroll
        for (int o = 16; o; o >>= 1) {
            #pragma unroll
            for (int k = 0; k < 4; k++)
                s[k] += __shfl_down_sync(0xffffffffu, s[k], o);
        }
        __shared__ float sh[4][8];
        if ((tid & 31) == 0) {
            #pragma unroll
            for (int k = 0; k < 4; k++) sh[k][tid >> 5] = s[k];
        }
        __syncthreads();
        if (tid < 8) {
            float v0 = sh[0][tid], v1 = sh[1][tid], v2 = sh[2][tid], v3 = sh[3][tid];
            #pragma unroll
            for (int o = 4; o; o >>= 1) {
                v0 += __shfl_down_sync(0xffu, v0, o);
                v1 += __shfl_down_sync(0xffu, v1, o);
                v2 += __shfl_down_sync(0xffu, v2, o);
                v3 += __shfl_down_sync(0xffu, v3, o);
            }
            if (tid == 0) {
                g_lse[r0]     = __logf(v0);
                g_lse[r0 + 1] = __logf(v1);
                g_lse[r0 + 2] = __logf(v2);
                g_lse[r0 + 3] = __logf(v3);
                __threadfence();
                atomicAdd(&g_done[prod_b], 1u);
            }
        }
    } else {
        // ================= consumer: 172 rows x 256 cols column pass ======
        if (tid == 0) {
            volatile unsigned* dp = g_done + cons_b;
            while (*dp < (unsigned)NPROD_PER_B) { __nanosleep(100); }
        }
        __syncthreads();
        __threadfence();   // acquire: order subsequent loads after flag

        __shared__ float sh_lse[CV];
        for (int i = tid; i < CV; i += TPB)
            sh_lse[i] = g_lse[cons_b * BV + cons_c * CV + i];
        __syncthreads();

        const float* col = out + ((size_t)cons_b * BV + cons_c * CV) * NS
                               + (cons_sc * SCW + tid);

        float sum  = 0.0f;
        float best = NEG_BIG;
        int   bi   = 0;

        int v = 0;
        #pragma unroll 1
        for (; v < 160; v += 16) {
            float x[16];
            #pragma unroll
            for (int j = 0; j < 16; j++)
                x[j] = __ldg(col + (size_t)(v + j) * NS);
            #pragma unroll
            for (int j = 0; j < 16; j++) {
                sum += __expf(x[j]);
                const float sc_ = x[j] - sh_lse[v + j];
                if (sc_ > best) { best = sc_; bi = v + j; }
            }
        }
        {   // remainder rows 160..171
            float x[12];
            #pragma unroll
            for (int j = 0; j < 12; j++)
                x[j] = __ldg(col + (size_t)(160 + j) * NS);
            #pragma unroll
            for (int j = 0; j < 12; j++) {
                sum += __expf(x[j]);
                const float sc_ = x[j] - sh_lse[160 + j];
                if (sc_ > best) { best = sc_; bi = 160 + j; }
            }
        }

        const int n = cons_b * NS + cons_sc * SCW + tid;
        g_psum [cons_c * NCOLS + n] = sum;
        g_pbest[cons_c * NCOLS + n] = best;
        g_pbi  [cons_c * NCOLS + n] = cons_c * CV + bi;
    }
}

// ---------------------------------------------------------------------------
// Combine: per column merge 3 chunk partials (fixed order -> exact first-max
// argmax), nll + penalty mask, deterministic reduction, fused finalize.
// ---------------------------------------------------------------------------
__global__ void __launch_bounds__(TPBC) k_comb(
    const float* __restrict__ out,
    const int*   __restrict__ target,
    const int*   __restrict__ ttype,
    const float* __restrict__ tvalue,
    const float* __restrict__ coeff,
    const float* __restrict__ harm,
    float*       __restrict__ res)
{
    const int n = blockIdx.x * TPBC + threadIdx.x;   // 0..65535
    const int b = n >> 11;
    const int s = n & (NS - 1);

    float sum = 0.0f, best = NEG_BIG;
    int bi = 0;
    #pragma unroll
    for (int c = 0; c < NCH; c++) {
        sum += g_psum[c * NCOLS + n];
        const float bb = g_pbest[c * NCOLS + n];
        if (bb > best) { best = bb; bi = g_pbi[c * NCOLS + n]; }
    }

    const int tgt = target[n];
    const float t_logit = __ldg(out + ((size_t)b * BV + tgt) * NS + s);
    const float nll = __logf(sum) - t_logit;

    // penalty mask
    const int   pt = __ldg(ttype  + bi), qt = __ldg(ttype  + tgt);
    const float pv = __ldg(tvalue + bi), qv = __ldg(tvalue + tgt);
    const float d  = fabsf(pv - qv);

    float pw = (d == 7.0f) ? __ldg(harm + 0)
             : (d == 5.0f) ? __ldg(harm + 1)
             : (d == 3.0f) ? __ldg(harm + 2)
             : (d == 4.0f) ? __ldg(harm + 3)
             : (d == 1.0f) ? __ldg(harm + 4)
             : (d == 2.0f) ? __ldg(harm + 5)
             :               __ldg(harm + 6);

    float w;
    if (pt != qt)       w = __ldg(coeff + 0);
    else if (pt == 0)   w = pw;
    else if (pt == 1)   w = __ldg(coeff + 1) * d * (1.0f / 160.0f);
    else if (pt == 2)   w = __ldg(coeff + 2) * d * (1.0f / 100.0f);
    else                w = __ldg(coeff + 3) * d * (1.0f / 128.0f);

    // block reduction (double), fixed order
    double dn = (double)nll, dm = (double)w;
    #pragma unroll
    for (int o = 16; o; o >>= 1) {
        dn += __shfl_down_sync(0xffffffffu, dn, o);
        dm += __shfl_down_sync(0xffffffffu, dm, o);
    }
    __shared__ double shn[TPBC / 32], shm[TPBC / 32];
    const int wid = threadIdx.x >> 5;
    if ((threadIdx.x & 31) == 0) { shn[wid] = dn; shm[wid] = dm; }
    __syncthreads();

    __shared__ bool s_last;
    if (threadIdx.x == 0) {
        double an = 0.0, am = 0.0;
        #pragma unroll
        for (int i = 0; i < TPBC / 32; i++) { an += shn[i]; am += shm[i]; }
        g_part_nll[blockIdx.x]  = an;
        g_part_mask[blockIdx.x] = am;
        __threadfence();
        unsigned prev = atomicAdd(&g_arrive, 1u);
        s_last = (prev == NBLKC - 1);
    }
    __syncthreads();

    if (s_last) {
        const int t = threadIdx.x;
        double an = 0.0, am = 0.0;
        #pragma unroll
        for (int k = 0; k < NBLKC / TPBC; k++) {
            an += g_part_nll[t + k * TPBC];
            am += g_part_mask[t + k * TPBC];
        }
        #pragma unroll
        for (int o = 16; o; o >>= 1) {
            an += __shfl_down_sync(0xffffffffu, an, o);
            am += __shfl_down_sync(0xffffffffu, am, o);
        }
        if ((t & 31) == 0) { shn[t >> 5] = an; shm[t >> 5] = am; }
        __syncthreads();
        if (t == 0) {
            double fn = 0.0, fm = 0.0;
            #pragma unroll
            for (int i = 0; i < TPBC / 32; i++) { fn += shn[i]; fm += shm[i]; }
            const double inv = 1.0 / (double)NCOLS;
            const double loss = fn * inv;
            res[0] = (float)(loss * (1.0 + fm * inv));
        }
    }
}

extern "C" void kernel_launch(void* const* d_in, const int* in_sizes, int n_in,
                              void* d_out, int out_size)
{
    const float* output  = (const float*)d_in[0];   // [32, 516, 2048] f32
    const int*   target  = (const int*)  d_in[1];   // [32, 2048] i32
    const int*   ttype   = (const int*)  d_in[2];   // [516] i32
    const float* tvalue  = (const float*)d_in[3];   // [516] f32
    const float* coeff   = (const float*)d_in[4];   // [4] f32
    const float* harm    = (const float*)d_in[5];   // [7] f32
    float* out = (float*)d_out;

    k_reset<<<1, 32>>>();
    k_fused<<<NTICK, TPB>>>(output);
    k_comb<<<NBLKC, TPBC>>>(output, target, ttype, tvalue, coeff, harm, out);
}